// round 17
// baseline (speedup 1.0000x reference)
#include <cuda_runtime.h>
#include <cuda_bf16.h>
#include <cstdint>

#define GS_FX 500.0f
#define TB 64                       // threads per block
#define TGB (TB)                    // gaussian-groups per block (4 gauss/thread)

__device__ __forceinline__ float clipf(float v, float lo, float hi) {
    return fminf(fmaxf(v, lo), hi);
}

__device__ __forceinline__ uint32_t smem_u32(const void* p) {
    return (uint32_t)__cvta_generic_to_shared(p);
}

#define BULK_S2G_POL(gptr, saddr, bytes, pol)                                  \
    asm volatile("cp.async.bulk.global.shared::cta.bulk_group.L2::cache_hint " \
                 "[%0], [%1], %2, %3;"                                         \
                 :: "l"(gptr), "r"(saddr), "r"(bytes), "l"(pol) : "memory")

#define BULK_G2S_POL(saddr, gptr, bytes, mbar, pol)                            \
    asm volatile("cp.async.bulk.shared::cta.global.mbarrier::complete_tx::bytes" \
                 ".L2::cache_hint [%0], [%1], %2, [%3], %4;"                   \
                 :: "r"(saddr), "l"(gptr), "r"(bytes), "r"(mbar), "l"(pol)     \
                 : "memory")

#define MBAR_WAIT_P0(mb)                                                        \
    asm volatile(                                                               \
        "{\n\t"                                                                 \
        ".reg .pred P;\n\t"                                                     \
        "GSW_%=:\n\t"                                                           \
        "mbarrier.try_wait.parity.acquire.cta.shared::cta.b64 P, [%0], 0, 0x989680;\n\t" \
        "@P bra GSD_%=;\n\t"                                                    \
        "bra GSW_%=;\n\t"                                                       \
        "GSD_%=:\n\t"                                                           \
        "}" :: "r"(mb) : "memory")

// ---------------------------------------------------------------------------
// R16 structure at HALF tile size again: 64 threads / 256 gaussians /
// ~12.5KB smem -> ~18 resident blocks per SM (vs 9): double the independent
// load/compute/store pipelines per SM covering each other's bubbles.
//   mb0: pos+scales (6KB) -> geometry starts as soon as it lands
//   mb1: colors+opac (4KB) -> phase 2; phase-1 store drain overlaps it
// L2 policies (champion): inputs evict_last f=0.75, outputs evict_first.
// ---------------------------------------------------------------------------
__global__ void __launch_bounds__(TB)
gs_tma_kernel(const float4* __restrict__ pos4,
              const float4* __restrict__ sc4,
              const float4* __restrict__ col4,
              const float4* __restrict__ op4,
              const float*  __restrict__ vm,
              const int*    __restrict__ wp,
              const int*    __restrict__ hp,
              float4* __restrict__ out4, int G)
{
    __shared__ alignas(16) float4 s_a[3 * TB];   // pos in  -> proj out
    __shared__ alignas(16) float4 s_b[4 * TB];   // scales in -> cov out
    __shared__ alignas(16) float4 s_c[3 * TB];   // colors in/out
    __shared__ alignas(16) float4 s_d[TB];       // opac in/out
    __shared__ alignas(16) float4 s_e[TB];       // valid out
    __shared__ alignas(8)  uint64_t mbar[2];

    int  t    = threadIdx.x;
    long base = (long)blockIdx.x * TGB;
    long g    = base + t;
    bool full = (base + TGB) <= (long)G;

    if (full) {
        if (t == 0) {
            asm volatile("mbarrier.init.shared.b64 [%0], 1;" :: "r"(smem_u32(&mbar[0])) : "memory");
            asm volatile("mbarrier.init.shared.b64 [%0], 1;" :: "r"(smem_u32(&mbar[1])) : "memory");
        }
        __syncthreads();
        if (t == 0) {
            uint64_t pol_pin;
            asm volatile("createpolicy.fractional.L2::evict_last.b64 %0, 0.75;"
                         : "=l"(pol_pin));
            uint32_t mb0 = smem_u32(&mbar[0]);
            uint32_t mb1 = smem_u32(&mbar[1]);
            asm volatile("mbarrier.arrive.expect_tx.shared.b64 _, [%0], %1;"
                         :: "r"(mb0), "r"(2u * 3 * TB * 16) : "memory");
            BULK_G2S_POL(smem_u32(s_a), (const void*)(pos4 + 3 * base), 3 * TB * 16, mb0, pol_pin);
            BULK_G2S_POL(smem_u32(s_b), (const void*)(sc4  + 3 * base), 3 * TB * 16, mb0, pol_pin);
            asm volatile("mbarrier.arrive.expect_tx.shared.b64 _, [%0], %1;"
                         :: "r"(mb1), "r"(4u * TB * 16) : "memory");
            BULK_G2S_POL(smem_u32(s_c), (const void*)(col4 + 3 * base), 3 * TB * 16, mb1, pol_pin);
            BULK_G2S_POL(smem_u32(s_d), (const void*)(op4  + base),          TB * 16, mb1, pol_pin);
        }
    }

    float W = (float)(*wp), H = (float)(*hp);
    float hw = W * 0.5f, hh = H * 0.5f;
    float xmax = W + 1000.0f, ymax = H + 1000.0f;

    if (full) {
        // ---------------- phase 1: geometry (needs only pos+scales) --------
        MBAR_WAIT_P0(smem_u32(&mbar[0]));
        float4 p0 = s_a[3 * t], p1 = s_a[3 * t + 1], p2 = s_a[3 * t + 2];
        float4 s0 = s_b[3 * t], s1 = s_b[3 * t + 1], s2 = s_b[3 * t + 2];

        float px[4] = {p0.x, p0.w, p1.z, p2.y};
        float py[4] = {p0.y, p1.x, p1.w, p2.z};
        float pz[4] = {p0.z, p1.y, p2.x, p2.w};
        float sx[4] = {s0.x, s0.w, s1.z, s2.y};
        float sy[4] = {s0.y, s1.x, s1.w, s2.z};

        float xs[4], ys[4], zs[4], c00[4], c11[4], vf[4];
#pragma unroll
        for (int j = 0; j < 4; j++) {
            float ax = px[j] - vm[3], ay = py[j] - vm[7], az = pz[j] - vm[11];
            float vx = clipf(fmaf(vm[0], ax, fmaf(vm[1], ay, vm[2]  * az)), -100.0f, 100.0f);
            float vy = clipf(fmaf(vm[4], ax, fmaf(vm[5], ay, vm[6]  * az)), -100.0f, 100.0f);
            float vz = clipf(fmaf(vm[8], ax, fmaf(vm[9], ay, vm[10] * az)), -100.0f, 100.0f);

            vf[j] = (vz > 0.1f && vz < 10.0f) ? 1.0f : 0.0f;

            float z   = clipf(vz, 0.1f, 10.0f);
            float inv = __fdividef(GS_FX, z);   // FX == FY

            xs[j] = clipf(fmaf(vx, inv, hw), -1000.0f, xmax);
            ys[j] = clipf(fmaf(-vy, inv, hh), -1000.0f, ymax);
            zs[j] = vz;

            float ssx = fmaxf(sx[j], 0.001f) * inv;
            float ssy = fmaxf(sy[j], 0.001f) * inv;
            c00[j] = clipf(fmaf(ssx, ssx, 1e-4f), 1e-6f, 1e6f);
            c11[j] = clipf(fmaf(ssy, ssy, 1e-4f), 1e-6f, 1e6f);
        }

        // s_b read(3t) -> write(4t) is cross-thread: one sync needed.
        __syncthreads();
        s_a[3 * t + 0] = make_float4(xs[0], ys[0], zs[0], xs[1]);
        s_a[3 * t + 1] = make_float4(ys[1], zs[1], xs[2], ys[2]);
        s_a[3 * t + 2] = make_float4(zs[2], xs[3], ys[3], zs[3]);
#pragma unroll
        for (int j = 0; j < 4; j++)
            s_b[4 * t + j] = make_float4(c00[j], 1e-6f, 1e-6f, c11[j]);
        s_e[t] = make_float4(vf[0], vf[1], vf[2], vf[3]);
        __syncthreads();

        if (t == 0) {
            uint64_t pol_out;
            asm volatile("createpolicy.fractional.L2::evict_first.b64 %0, 1.0;"
                         : "=l"(pol_out));
            asm volatile("fence.proxy.async.shared::cta;" ::: "memory");
            BULK_S2G_POL(out4 + 3 * base,          smem_u32(s_a), 3 * TB * 16, pol_out);
            BULK_S2G_POL(out4 + 3L * G + 4 * base, smem_u32(s_b), 4 * TB * 16, pol_out);
            BULK_S2G_POL(out4 + 11L * G + base,    smem_u32(s_e),     TB * 16, pol_out);
            asm volatile("cp.async.bulk.commit_group;" ::: "memory");
            // no wait: geometry drain overlaps phase 2
        }

        // ---------------- phase 2: colors + opacity (sync-free rewrite) ----
        MBAR_WAIT_P0(smem_u32(&mbar[1]));
        float4 c0 = s_c[3 * t], c1 = s_c[3 * t + 1], c2 = s_c[3 * t + 2];
        float4 o4 = s_d[t];

        c0.x = clipf(c0.x,0.f,1.f); c0.y = clipf(c0.y,0.f,1.f);
        c0.z = clipf(c0.z,0.f,1.f); c0.w = clipf(c0.w,0.f,1.f);
        c1.x = clipf(c1.x,0.f,1.f); c1.y = clipf(c1.y,0.f,1.f);
        c1.z = clipf(c1.z,0.f,1.f); c1.w = clipf(c1.w,0.f,1.f);
        c2.x = clipf(c2.x,0.f,1.f); c2.y = clipf(c2.y,0.f,1.f);
        c2.z = clipf(c2.z,0.f,1.f); c2.w = clipf(c2.w,0.f,1.f);

        o4.x = __fdividef(1.0f, 1.0f + __expf(-o4.x));
        o4.y = __fdividef(1.0f, 1.0f + __expf(-o4.y));
        o4.z = __fdividef(1.0f, 1.0f + __expf(-o4.z));
        o4.w = __fdividef(1.0f, 1.0f + __expf(-o4.w));

        // identity-addressed rewrites: no cross-thread hazard, no sync needed
        s_c[3 * t + 0] = c0;
        s_c[3 * t + 1] = c1;
        s_c[3 * t + 2] = c2;
        s_d[t] = o4;
        __syncthreads();

        if (t == 0) {
            uint64_t pol_out;
            asm volatile("createpolicy.fractional.L2::evict_first.b64 %0, 1.0;"
                         : "=l"(pol_out));
            asm volatile("fence.proxy.async.shared::cta;" ::: "memory");
            BULK_S2G_POL(out4 + 7L * G + 3 * base, smem_u32(s_c), 3 * TB * 16, pol_out);
            BULK_S2G_POL(out4 + 10L * G + base,    smem_u32(s_d),     TB * 16, pol_out);
            asm volatile("cp.async.bulk.commit_group;" ::: "memory");
            asm volatile("cp.async.bulk.wait_group 0;" ::: "memory");
        }
        __syncthreads();
    } else if (g < G) {
        // tail block: direct strided path
        float4 p0 = pos4[3 * g], p1 = pos4[3 * g + 1], p2 = pos4[3 * g + 2];
        float4 s0 = sc4[3 * g],  s1 = sc4[3 * g + 1],  s2 = sc4[3 * g + 2];
        float4 c0 = col4[3 * g], c1 = col4[3 * g + 1], c2 = col4[3 * g + 2];
        float4 o4 = op4[g];

        float px[4] = {p0.x, p0.w, p1.z, p2.y};
        float py[4] = {p0.y, p1.x, p1.w, p2.z};
        float pz[4] = {p0.z, p1.y, p2.x, p2.w};
        float sx[4] = {s0.x, s0.w, s1.z, s2.y};
        float sy[4] = {s0.y, s1.x, s1.w, s2.z};

        float xs[4], ys[4], zs[4], c00[4], c11[4], vf[4];
#pragma unroll
        for (int j = 0; j < 4; j++) {
            float ax = px[j] - vm[3], ay = py[j] - vm[7], az = pz[j] - vm[11];
            float vx = clipf(fmaf(vm[0], ax, fmaf(vm[1], ay, vm[2]  * az)), -100.0f, 100.0f);
            float vy = clipf(fmaf(vm[4], ax, fmaf(vm[5], ay, vm[6]  * az)), -100.0f, 100.0f);
            float vz = clipf(fmaf(vm[8], ax, fmaf(vm[9], ay, vm[10] * az)), -100.0f, 100.0f);
            vf[j] = (vz > 0.1f && vz < 10.0f) ? 1.0f : 0.0f;
            float z   = clipf(vz, 0.1f, 10.0f);
            float inv = __fdividef(GS_FX, z);
            xs[j] = clipf(fmaf(vx, inv, hw), -1000.0f, xmax);
            ys[j] = clipf(fmaf(-vy, inv, hh), -1000.0f, ymax);
            zs[j] = vz;
            float ssx = fmaxf(sx[j], 0.001f) * inv;
            float ssy = fmaxf(sy[j], 0.001f) * inv;
            c00[j] = clipf(fmaf(ssx, ssx, 1e-4f), 1e-6f, 1e6f);
            c11[j] = clipf(fmaf(ssy, ssy, 1e-4f), 1e-6f, 1e6f);
        }

        out4[3 * g + 0] = make_float4(xs[0], ys[0], zs[0], xs[1]);
        out4[3 * g + 1] = make_float4(ys[1], zs[1], xs[2], ys[2]);
        out4[3 * g + 2] = make_float4(zs[2], xs[3], ys[3], zs[3]);
        long cb = 3L * G;
#pragma unroll
        for (int j = 0; j < 4; j++)
            out4[cb + 4L * g + j] = make_float4(c00[j], 1e-6f, 1e-6f, c11[j]);
        long kb = 7L * G;
        out4[kb + 3 * g + 0] = make_float4(clipf(c0.x,0.f,1.f), clipf(c0.y,0.f,1.f),
                                           clipf(c0.z,0.f,1.f), clipf(c0.w,0.f,1.f));
        out4[kb + 3 * g + 1] = make_float4(clipf(c1.x,0.f,1.f), clipf(c1.y,0.f,1.f),
                                           clipf(c1.z,0.f,1.f), clipf(c1.w,0.f,1.f));
        out4[kb + 3 * g + 2] = make_float4(clipf(c2.x,0.f,1.f), clipf(c2.y,0.f,1.f),
                                           clipf(c2.z,0.f,1.f), clipf(c2.w,0.f,1.f));
        o4.x = __fdividef(1.0f, 1.0f + __expf(-o4.x));
        o4.y = __fdividef(1.0f, 1.0f + __expf(-o4.y));
        o4.z = __fdividef(1.0f, 1.0f + __expf(-o4.z));
        o4.w = __fdividef(1.0f, 1.0f + __expf(-o4.w));
        out4[10L * G + g] = o4;
        out4[11L * G + g] = make_float4(vf[0], vf[1], vf[2], vf[3]);
    }
}

// ---------------------------------------------------------------------------
// Scalar fallback for N % 4 != 0 (not expected with N = 4,000,000).
// ---------------------------------------------------------------------------
__global__ void __launch_bounds__(256)
gs_scalar_kernel(const float* __restrict__ pos,
                 const float* __restrict__ sc,
                 const float* __restrict__ col,
                 const float* __restrict__ op,
                 const float* __restrict__ vm,
                 const int*   __restrict__ wp,
                 const int*   __restrict__ hp,
                 float* __restrict__ out, int N)
{
    int i = blockIdx.x * blockDim.x + threadIdx.x;
    if (i >= N) return;

    float W = (float)(*wp), H = (float)(*hp);
    float hw = W * 0.5f, hh = H * 0.5f;
    float xmax = W + 1000.0f, ymax = H + 1000.0f;

    float ax = pos[3*i] - vm[3], ay = pos[3*i+1] - vm[7], az = pos[3*i+2] - vm[11];
    float vx = clipf(fmaf(vm[0], ax, fmaf(vm[1], ay, vm[2]  * az)), -100.0f, 100.0f);
    float vy = clipf(fmaf(vm[4], ax, fmaf(vm[5], ay, vm[6]  * az)), -100.0f, 100.0f);
    float vz = clipf(fmaf(vm[8], ax, fmaf(vm[9], ay, vm[10] * az)), -100.0f, 100.0f);

    float z   = clipf(vz, 0.1f, 10.0f);
    float inv = __fdividef(GS_FX, z);

    long n = N;
    out[3*i+0] = clipf(fmaf(vx, inv, hw), -1000.0f, xmax);
    out[3*i+1] = clipf(fmaf(-vy, inv, hh), -1000.0f, ymax);
    out[3*i+2] = vz;

    float ssx = fmaxf(sc[3*i],   0.001f) * inv;
    float ssy = fmaxf(sc[3*i+1], 0.001f) * inv;
    out[3*n + 4L*i + 0] = clipf(fmaf(ssx, ssx, 1e-4f), 1e-6f, 1e6f);
    out[3*n + 4L*i + 1] = 1e-6f;
    out[3*n + 4L*i + 2] = 1e-6f;
    out[3*n + 4L*i + 3] = clipf(fmaf(ssy, ssy, 1e-4f), 1e-6f, 1e6f);

    out[7*n + 3L*i + 0] = clipf(col[3*i+0], 0.f, 1.f);
    out[7*n + 3L*i + 1] = clipf(col[3*i+1], 0.f, 1.f);
    out[7*n + 3L*i + 2] = clipf(col[3*i+2], 0.f, 1.f);

    out[10*n + i] = __fdividef(1.0f, 1.0f + __expf(-op[i]));
    out[11*n + i] = (vz > 0.1f && vz < 10.0f) ? 1.0f : 0.0f;
}

extern "C" void kernel_launch(void* const* d_in, const int* in_sizes, int n_in,
                              void* d_out, int out_size)
{
    const float* positions = (const float*)d_in[0];
    const float* scales    = (const float*)d_in[1];
    // d_in[2] rotations: unused by the reference math
    const float* colors    = (const float*)d_in[3];
    const float* opac      = (const float*)d_in[4];
    const float* viewmat   = (const float*)d_in[5];
    // d_in[6] projmat: unused
    const int*   wp        = (const int*)d_in[7];
    const int*   hp        = (const int*)d_in[8];
    float* out = (float*)d_out;

    int N = in_sizes[0] / 3;

    if ((N & 3) == 0) {
        int G = N >> 2;
        int blocks = (G + TGB - 1) / TGB;
        gs_tma_kernel<<<blocks, TB>>>(
            (const float4*)positions, (const float4*)scales,
            (const float4*)colors, (const float4*)opac,
            viewmat, wp, hp, (float4*)out, G);
    } else {
        int threads = 256;
        int blocks = (N + threads - 1) / threads;
        gs_scalar_kernel<<<blocks, threads>>>(
            positions, scales, colors, opac, viewmat, wp, hp, out, N);
    }
}